// round 16
// baseline (speedup 1.0000x reference)
#include <cuda_runtime.h>
#include <cuda_bf16.h>
#include <cstdint>

// Problem constants
#define B_  2
#define S_  2048
#define D_  1024
#define H_  8
#define E_  128
#define KW_ 16
#define M_  (B_ * S_)        // 4096 tokens
#define N1_ (3 * H_ * E_)    // 3072 fused qkv output cols
#define K_  D_               // 1024 reduction dim

// Scratch (static device memory)
__device__ float g_q[B_ * H_ * S_ * E_];       // [b][h][s][e]
__device__ float g_k[B_ * H_ * S_ * E_];
__device__ float g_v[B_ * H_ * S_ * E_];
__device__ float g_attn[B_ * S_ * H_ * E_];    // [b][s][h][e]

// ---------------------------------------------------------------------------
// f32x2 packed FMA helpers (validated round 11/15)
// ---------------------------------------------------------------------------
typedef unsigned long long u64b;

__device__ __forceinline__ void fma2(u64b& c, u64b a, u64b b) {
    asm("fma.rn.f32x2 %0, %1, %2, %0;" : "+l"(c) : "l"(a), "l"(b));
}
__device__ __forceinline__ float2 unpack2(u64b v) {
    float2 f;
    asm("mov.b64 {%0, %1}, %2;" : "=f"(f.x), "=f"(f.y) : "l"(v));
    return f;
}

// ---------------------------------------------------------------------------
// SGEMM core: 128x128 CTA tile, BK=8, 256 threads, 8x8 thread tile.
// A stored DUPLICATED in smem: As2[kk][2r]=As2[kk][2r+1]=a_r, so one LDS.128
// yields two packed (a,a) f32x2 operands -> zero pack movs in the hot loop.
// B columns per thread: {4t..4t+3} U {64+4t..64+4t+3} (conflict-free LDS.64).
// 2-stage double buffer, 1 syncthreads per k-tile.
// Assumes bm, bn, tid already defined. BPTR_BASE points at (k-row 0, this
// CTA's column base); row stride LDB.
// ---------------------------------------------------------------------------
#define GEMM_CORE(APTR_BASE, BPTR_BASE, LDB)                                    \
    __shared__ float As2[2][8][256];                                            \
    __shared__ float Bs[2][8][128];                                             \
    const int arow = tid >> 1;            /* 0..127 */                          \
    const int acol = (tid & 1) * 4;       /* 0 or 4 */                          \
    const int brow = tid >> 5;            /* 0..7   */                          \
    const int bcol = (tid & 31) * 4;      /* 0..124 */                          \
    const int tm = (tid >> 4) * 8;        /* rows tm..tm+7 */                   \
    const int tc = (tid & 15) * 4;        /* cols tc..tc+3 and 64+tc..+3 */     \
    u64b acc2[8][4];                                                            \
    _Pragma("unroll")                                                           \
    for (int i = 0; i < 8; i++)                                                 \
        _Pragma("unroll")                                                       \
        for (int j = 0; j < 4; j++) acc2[i][j] = 0ull;                          \
    const float* aptr = (APTR_BASE) + (size_t)(bm + arow) * K_ + acol;          \
    const float* bptr = (BPTR_BASE) + (size_t)brow * (LDB) + bcol;              \
    float4 a_nxt = *(const float4*)aptr;                                        \
    float4 b_nxt = *(const float4*)bptr;                                        \
    *(float2*)&As2[0][acol + 0][2 * arow] = make_float2(a_nxt.x, a_nxt.x);      \
    *(float2*)&As2[0][acol + 1][2 * arow] = make_float2(a_nxt.y, a_nxt.y);      \
    *(float2*)&As2[0][acol + 2][2 * arow] = make_float2(a_nxt.z, a_nxt.z);      \
    *(float2*)&As2[0][acol + 3][2 * arow] = make_float2(a_nxt.w, a_nxt.w);      \
    *(float4*)&Bs[0][brow][bcol] = b_nxt;                                       \
    __syncthreads();                                                            \
    _Pragma("unroll 1")                                                         \
    for (int k0 = 0; k0 < K_; k0 += 8) {                                        \
        const int buf = (k0 >> 3) & 1;                                          \
        if (k0 + 8 < K_) {                                                      \
            a_nxt = *(const float4*)(aptr + k0 + 8);                            \
            b_nxt = *(const float4*)(bptr + (size_t)(k0 + 8) * (LDB));          \
        }                                                                       \
        _Pragma("unroll")                                                       \
        for (int kk = 0; kk < 8; kk++) {                                        \
            u64b aa[8];                                                         \
            _Pragma("unroll")                                                   \
            for (int g = 0; g < 4; g++) {                                       \
                float4 av = *(const float4*)&As2[buf][kk][2 * tm + 4 * g];      \
                aa[2 * g + 0] = *(const u64b*)&av.x;                            \
                aa[2 * g + 1] = *(const u64b*)&av.z;                            \
            }                                                                   \
            u64b bb0 = *(const u64b*)&Bs[buf][kk][tc];                          \
            u64b bb1 = *(const u64b*)&Bs[buf][kk][tc + 2];                      \
            u64b bb2 = *(const u64b*)&Bs[buf][kk][tc + 64];                     \
            u64b bb3 = *(const u64b*)&Bs[buf][kk][tc + 66];                     \
            _Pragma("unroll")                                                   \
            for (int i = 0; i < 8; i++) {                                       \
                fma2(acc2[i][0], aa[i], bb0);                                   \
                fma2(acc2[i][1], aa[i], bb1);                                   \
                fma2(acc2[i][2], aa[i], bb2);                                   \
                fma2(acc2[i][3], aa[i], bb3);                                   \
            }                                                                   \
        }                                                                       \
        if (k0 + 8 < K_) {                                                      \
            const int nb = buf ^ 1;                                             \
            *(float2*)&As2[nb][acol + 0][2 * arow] = make_float2(a_nxt.x, a_nxt.x); \
            *(float2*)&As2[nb][acol + 1][2 * arow] = make_float2(a_nxt.y, a_nxt.y); \
            *(float2*)&As2[nb][acol + 2][2 * arow] = make_float2(a_nxt.z, a_nxt.z); \
            *(float2*)&As2[nb][acol + 3][2 * arow] = make_float2(a_nxt.w, a_nxt.w); \
            *(float4*)&Bs[nb][brow][bcol] = b_nxt;                              \
        }                                                                       \
        __syncthreads();                                                        \
    }

// ---------------------------------------------------------------------------
// Fused QKV SGEMM reading Wq/Wk/Wv DIRECTLY (no packing pass).
// CTA column tile = one (proj, head): B[k][e] = Wsel[h][d=k][e], stride E_.
// Epilogue scatters q/k/v + bias into [b,h,s,e].
// ---------------------------------------------------------------------------
__global__ __launch_bounds__(256, 2) void gemm_qkv_kernel(
    const float* __restrict__ x,
    const float* __restrict__ Wq, const float* __restrict__ Wk,
    const float* __restrict__ Wv,
    const float* __restrict__ bq, const float* __restrict__ bk,
    const float* __restrict__ bv) {
    const int tid = threadIdx.x;
    const int bm = blockIdx.y * 128;
    const int bn = blockIdx.x * 128;
    const int proj = bn >> 10;
    const int h    = (bn >> 7) & 7;
    const float* Wsel = ((proj == 0) ? Wq : (proj == 1) ? Wk : Wv)
                      + (size_t)h * D_ * E_;

    GEMM_CORE(x, Wsel, E_)

    const float* bias = ((proj == 0) ? bq : (proj == 1) ? bk : bv) + h * E_;
    float* dstbase    = (proj == 0) ? g_q : (proj == 1) ? g_k : g_v;

    float4 bia0 = *(const float4*)(bias + tc);
    float4 bia1 = *(const float4*)(bias + tc + 64);

#pragma unroll
    for (int i = 0; i < 8; i++) {
        int m = bm + tm + i;
        int b = m >> 11;
        int s = m & (S_ - 1);
        float* row = dstbase + ((size_t)(b * H_ + h) * S_ + s) * E_;
        float2 p0 = unpack2(acc2[i][0]);
        float2 p1 = unpack2(acc2[i][1]);
        float2 p2 = unpack2(acc2[i][2]);
        float2 p3 = unpack2(acc2[i][3]);
        float4 v0 = {p0.x + bia0.x, p0.y + bia0.y, p1.x + bia0.z, p1.y + bia0.w};
        float4 v1 = {p2.x + bia1.x, p2.y + bia1.y, p3.x + bia1.z, p3.y + bia1.w};
        *(float4*)(row + tc) = v0;
        *(float4*)(row + tc + 64) = v1;
    }
}

// ---------------------------------------------------------------------------
// Output projection SGEMM: out + bo (Wo read directly, row stride D_)
// ---------------------------------------------------------------------------
__global__ __launch_bounds__(256, 2) void gemm_out_kernel(
    const float* __restrict__ Wo,
    const float* __restrict__ bo,
    float* __restrict__ out) {
    const int tid = threadIdx.x;
    const int bm = blockIdx.y * 128;
    const int bn = blockIdx.x * 128;

    GEMM_CORE(g_attn, Wo + bn, D_)

    float4 bia0 = *(const float4*)(bo + bn + tc);
    float4 bia1 = *(const float4*)(bo + bn + tc + 64);

#pragma unroll
    for (int i = 0; i < 8; i++) {
        int m = bm + tm + i;
        float* row = out + (size_t)m * D_ + bn;
        float2 p0 = unpack2(acc2[i][0]);
        float2 p1 = unpack2(acc2[i][1]);
        float2 p2 = unpack2(acc2[i][2]);
        float2 p3 = unpack2(acc2[i][3]);
        float4 v0 = {p0.x + bia0.x, p0.y + bia0.y, p1.x + bia0.z, p1.y + bia0.w};
        float4 v1 = {p2.x + bia1.x, p2.y + bia1.y, p3.x + bia1.z, p3.y + bia1.w};
        *(float4*)(row + tc) = v0;
        *(float4*)(row + tc + 64) = v1;
    }
}

// ---------------------------------------------------------------------------
// Dilated local attention (round-1 verbatim; passing)
// ---------------------------------------------------------------------------
__global__ __launch_bounds__(256) void attn_kernel(
    const float* __restrict__ bk,
    const float* __restrict__ bv,
    const int*   __restrict__ dilations) {
    const int warp = (blockIdx.x * blockDim.x + threadIdx.x) >> 5;
    const int lane = threadIdx.x & 31;
    const int s  = warp & (S_ - 1);
    const int bh = warp >> 11;
    const int h  = bh & (H_ - 1);
    const int b  = bh >> 3;

    const int d   = dilations[h];
    const int off = (d * (KW_ - 1)) >> 1;

    const float* qp    = g_q + ((size_t)(b * H_ + h) * S_ + s) * E_;
    const float* kbase = g_k + (size_t)(b * H_ + h) * S_ * E_;
    const float* vbase = g_v + (size_t)(b * H_ + h) * S_ * E_;

    const float4 qv    = *(const float4*)(qp + lane * 4);
    const float4 kbias = *(const float4*)(bk + h * E_ + lane * 4);
    const float4 vbias = *(const float4*)(bv + h * E_ + lane * 4);

    float logits[KW_];
#pragma unroll
    for (int j = 0; j < KW_; j++) {
        int pos = s + d * j - off;
        bool valid = (pos >= 0) && (pos < S_);
        float4 kv = valid ? *(const float4*)(kbase + (size_t)pos * E_ + lane * 4)
                          : kbias;
        float p = qv.x * kv.x + qv.y * kv.y + qv.z * kv.z + qv.w * kv.w;
        p += __shfl_xor_sync(0xFFFFFFFFu, p, 16);
        p += __shfl_xor_sync(0xFFFFFFFFu, p, 8);
        p += __shfl_xor_sync(0xFFFFFFFFu, p, 4);
        p += __shfl_xor_sync(0xFFFFFFFFu, p, 2);
        p += __shfl_xor_sync(0xFFFFFFFFu, p, 1);
        logits[j] = p;
    }

    float mx = logits[0];
#pragma unroll
    for (int j = 1; j < KW_; j++) mx = fmaxf(mx, logits[j]);
    float ssum = 0.f;
    float w[KW_];
#pragma unroll
    for (int j = 0; j < KW_; j++) {
        w[j] = __expf(logits[j] - mx);
        ssum += w[j];
    }
    const float scale = (1.0f / ssum) * 0.08838834764831845f;  // 1/sqrt(128)

    float4 acc = {0.f, 0.f, 0.f, 0.f};
#pragma unroll
    for (int j = 0; j < KW_; j++) {
        int pos = s + d * j - off;
        bool valid = (pos >= 0) && (pos < S_);
        float4 vv = valid ? *(const float4*)(vbase + (size_t)pos * E_ + lane * 4)
                          : vbias;
        float wj = w[j] * scale;
        acc.x += wj * vv.x;
        acc.y += wj * vv.y;
        acc.z += wj * vv.z;
        acc.w += wj * vv.w;
    }

    float* outp = g_attn + ((size_t)(b * S_ + s) * H_ + h) * E_ + lane * 4;
    *(float4*)outp = acc;
}

// ---------------------------------------------------------------------------
// Launch — inputs: x, Wq, bq, Wk, bk, Wv, bv, Wo, bo, dilations
// ---------------------------------------------------------------------------
extern "C" void kernel_launch(void* const* d_in, const int* in_sizes, int n_in,
                              void* d_out, int out_size) {
    const float* x   = (const float*)d_in[0];
    const float* Wq  = (const float*)d_in[1];
    const float* bq  = (const float*)d_in[2];
    const float* Wk  = (const float*)d_in[3];
    const float* bk  = (const float*)d_in[4];
    const float* Wv  = (const float*)d_in[5];
    const float* bv  = (const float*)d_in[6];
    const float* Wo  = (const float*)d_in[7];
    const float* bo  = (const float*)d_in[8];
    const int*   dil = (const int*)d_in[9];
    float* out = (float*)d_out;

    // 1) fused qkv projection (direct weight read, no packing pass)
    {
        dim3 grid(N1_ / 128, M_ / 128);  // (24, 32)
        gemm_qkv_kernel<<<grid, 256>>>(x, Wq, Wk, Wv, bq, bk, bv);
    }
    // 2) windowed attention
    {
        int warps = B_ * H_ * S_;        // 32768
        attn_kernel<<<warps / 8, 256>>>(bk, bv, dil);
    }
    // 3) output projection
    {
        dim3 grid(D_ / 128, M_ / 128);   // (8, 32)
        gemm_out_kernel<<<grid, 256>>>(Wo, bo, out);
    }
}